// round 5
// baseline (speedup 1.0000x reference)
#include <cuda_runtime.h>
#include <cuda_bf16.h>
#include <cstdint>

// Shapes: query (N,T,C,L)=(32,64,256,64) fp32; key (T,N,C); out (T,N,C)
#define N_ 32
#define T_ 64
#define C_ 256
#define L_ 64
#define CHUNK_FLOATS (C_ * L_)          // 16384 floats = 64KB per (n,t)

__device__ float g_part[N_ * T_ * L_];  // per-(n,t) partial scores
__device__ float g_probs[N_ * L_];      // softmax probs per n
__device__ int   g_count[N_];           // pass1 arrivals  (zero-init, self-cleaning)
__device__ int   g_flag[N_];            // softmax-ready flag
__device__ int   g_done[N_];            // pass2 completions (last one resets all)

// ---------------------------------------------------------------------------
// Fused kernel. One block per (n,t)=b, 256 threads, 64KB dynamic smem.
//   1) cp.async the 64KB q-chunk into smem (DRAM read happens ONCE).
//   2) partial scores from smem; atomic arrival count per n.
//   3) 64th arriving block reduces over t + softmax -> g_probs, sets flag.
//      Peers spin (thread 0 only, nanosleep backoff).
//   4) output pass re-reads the SAME smem tile -> zero second DRAM pass.
//   5) self-clean sync state for the next graph replay.
// ---------------------------------------------------------------------------
__global__ __launch_bounds__(256) void k_fused(const float* __restrict__ q,
                                               const float* __restrict__ key,
                                               float* __restrict__ out) {
    extern __shared__ float qs[];                // [C_][L_] contiguous, 64KB
    __shared__ float2 red[8][32];
    __shared__ float  s_scratch[L_];
    __shared__ float  s_red2[4];
    __shared__ int    s_islast;

    const int b = blockIdx.x;
    const int n = b >> 6;
    const int t = b & 63;
    const int tid = threadIdx.x;
    const int w = tid >> 5;
    const int lane = tid & 31;

    // ---- stage q chunk: 4096 float4, 16 per thread, coalesced cp.async ----
    {
        const float4* __restrict__ src =
            reinterpret_cast<const float4*>(q + (size_t)b * CHUNK_FLOATS);
        uint32_t sbase = (uint32_t)__cvta_generic_to_shared(qs);
        #pragma unroll
        for (int i = 0; i < 16; ++i) {
            const int idx = tid + (i << 8);
            asm volatile("cp.async.cg.shared.global [%0], [%1], 16;\n"
                         :: "r"(sbase + idx * 16), "l"(src + idx));
        }
        asm volatile("cp.async.commit_group;\n");
    }

    // overlap: preload this warp's 32 key values (one per lane)
    const float kreg = key[((size_t)t * N_ + n) * C_ + (w << 5) + lane];

    asm volatile("cp.async.wait_group 0;\n");
    __syncthreads();

    // ---- pass 1: partial scores from smem ----
    const float2* __restrict__ qs2 = reinterpret_cast<const float2*>(qs);
    float2 acc = make_float2(0.f, 0.f);
    #pragma unroll 8
    for (int i = 0; i < 32; ++i) {
        const float kv = __shfl_sync(0xffffffffu, kreg, i);
        const float2 qv = qs2[((w << 5) + i) * 32 + lane];
        acc.x = fmaf(kv, qv.x, acc.x);
        acc.y = fmaf(kv, qv.y, acc.y);
    }
    red[w][lane] = acc;
    __syncthreads();
    if (tid < 32) {
        float2 tot = red[0][lane];
        #pragma unroll
        for (int j = 1; j < 8; ++j) {
            tot.x += red[j][lane].x;
            tot.y += red[j][lane].y;
        }
        reinterpret_cast<float2*>(g_part + (size_t)b * L_)[lane] = tot;
        __threadfence();
    }
    __syncthreads();

    if (tid == 0) {
        const int old = atomicAdd(&g_count[n], 1);
        s_islast = (old == T_ - 1);
    }
    __syncthreads();

    if (s_islast) {
        // ---- this block saw all 64 partials: reduce over t + softmax ----
        if (tid < L_) {
            float s = 0.f;
            const float* __restrict__ p = g_part + (size_t)n * T_ * L_ + tid;
            #pragma unroll
            for (int tt = 0; tt < T_; ++tt) s += p[(size_t)tt * L_];
            s_scratch[tid] = s;

            float m = s;
            #pragma unroll
            for (int off = 16; off; off >>= 1)
                m = fmaxf(m, __shfl_xor_sync(0xffffffffu, m, off));
            if (lane == 0) s_red2[w] = m;
        }
        __syncthreads();
        if (tid < L_) {
            const float m = fmaxf(s_red2[0], s_red2[1]);
            const float e = __expf(s_scratch[tid] - m);
            s_scratch[tid] = e;
            float sum = e;
            #pragma unroll
            for (int off = 16; off; off >>= 1)
                sum += __shfl_xor_sync(0xffffffffu, sum, off);
            if (lane == 0) s_red2[2 + w] = sum;
        }
        __syncthreads();
        if (tid < L_) {
            const float inv = 1.f / (s_red2[2] + s_red2[3]);
            g_probs[n * L_ + tid] = s_scratch[tid] * inv;
        }
        __syncthreads();
        if (tid == 0) {
            __threadfence();
            atomicExch(&g_flag[n], 1);
        }
    } else {
        // ---- wait for softmax of this n ----
        if (tid == 0) {
            while (atomicAdd(&g_flag[n], 0) == 0) __nanosleep(64);
            __threadfence();
        }
        __syncthreads();
    }

    // ---- pass 2: out[t,n,c] = sum_l qs[c][l] * probs[n][l] (smem only) ----
    const float2 pp = reinterpret_cast<const float2*>(g_probs + n * L_)[lane];
    float* __restrict__ ob = out + ((size_t)t * N_ + n) * C_;
    #pragma unroll 4
    for (int i = 0; i < 32; ++i) {
        const int c = (w << 5) + i;
        const float2 qv = qs2[c * 32 + lane];
        float v = fmaf(qv.x, pp.x, qv.y * pp.y);
        #pragma unroll
        for (int off = 16; off; off >>= 1)
            v += __shfl_xor_sync(0xffffffffu, v, off);
        if (lane == 0) ob[c] = v;
    }

    // ---- self-clean sync state for next launch (graph replay) ----
    __syncthreads();
    if (tid == 0) {
        const int old = atomicAdd(&g_done[n], 1);
        if (old == T_ - 1) {
            g_flag[n] = 0;
            g_count[n] = 0;
            g_done[n] = 0;
        }
    }
}

extern "C" void kernel_launch(void* const* d_in, const int* in_sizes, int n_in,
                              void* d_out, int out_size) {
    const float* q   = (const float*)d_in[0];
    const float* key = (const float*)d_in[1];
    float* out = (float*)d_out;

    cudaFuncSetAttribute(k_fused, cudaFuncAttributeMaxDynamicSharedMemorySize,
                         CHUNK_FLOATS * sizeof(float));
    k_fused<<<N_ * T_, 256, CHUNK_FLOATS * sizeof(float)>>>(q, key, out);
}